// round 1
// baseline (speedup 1.0000x reference)
#include <cuda_runtime.h>
#include <cstdint>

#define M_MOL 64
#define N_ATM 512
#define RC2 49.0f      // (cutoff + shell)^2 = 7^2
#define I_TILE 8
#define NTHREADS 256

__global__ __launch_bounds__(NTHREADS) void nbl_kernel(
    const float* __restrict__ pos,   // [64, 512, 3]
    float* __restrict__ out)         // [64, 512, 512, 3]
{
    __shared__ float sp[N_ATM * 3];  // this molecule's positions, 6 KB

    const int m = blockIdx.y;
    const float* pm = pos + (size_t)m * N_ATM * 3;

    // cooperative load of the molecule's positions into smem
    for (int t = threadIdx.x; t < N_ATM * 3; t += NTHREADS)
        sp[t] = pm[t];
    __syncthreads();

    const int i0 = blockIdx.x * I_TILE;

    #pragma unroll
    for (int ii = 0; ii < I_TILE; ii++) {
        const int i = i0 + ii;
        // broadcast read of pos_i (all lanes same address -> free)
        const float xi = sp[i * 3 + 0];
        const float yi = sp[i * 3 + 1];
        const float zi = sp[i * 3 + 2];

        float* orow = out + ((size_t)(m * N_ATM + i)) * N_ATM * 3;

        #pragma unroll
        for (int jb = 0; jb < N_ATM / NTHREADS; jb++) {
            const int j = jb * NTHREADS + threadIdx.x;
            // conflict-free: bank(3j+c) mod 32, gcd(3,32)=1
            const float dx = sp[j * 3 + 0] - xi;
            const float dy = sp[j * 3 + 1] - yi;
            const float dz = sp[j * 3 + 2] - zi;
            const float d2 = dx * dx + dy * dy + dz * dz;
            const bool keep = (d2 < RC2) && (j != i);

            // streaming stores: output is write-once, larger than L2
            __stcs(&orow[j * 3 + 0], keep ? dx : 0.0f);
            __stcs(&orow[j * 3 + 1], keep ? dy : 0.0f);
            __stcs(&orow[j * 3 + 2], keep ? dz : 0.0f);
        }
    }
}

extern "C" void kernel_launch(void* const* d_in, const int* in_sizes, int n_in,
                              void* d_out, int out_size)
{
    const float* pos = (const float*)d_in[0];
    float* out = (float*)d_out;

    dim3 grid(N_ATM / I_TILE, M_MOL);   // (64, 64)
    nbl_kernel<<<grid, NTHREADS>>>(pos, out);
}